// round 4
// baseline (speedup 1.0000x reference)
#include <cuda_runtime.h>
#include <cuda_bf16.h>
#include <cstdint>

#define BB 64
#define II 128
#define AA 16
#define HH 1024
#define BH (BB*HH)
#define GB 8            // batches per L2-resident group
#define NGROUPS (BB/GB)

// scratch (static __device__ — no allocations)
__device__ float g_so[BH];              // sign_j * output[b,j]
__device__ float g_ff[BH];              // b_h + relu(x)@|W_x|^T + relu(aux)@|W_aux|^T
__device__ unsigned int g_gq[HH*HH];    // packed bf16: lo = 0.02*|W_h|, hi = |kappa|

// ---------------- prep: pack (0.02*|W_h|, |kappa|) as bf16x2 ----------------
__global__ void prep_gq(const float* __restrict__ Wh, const float* __restrict__ kap) {
    int idx = blockIdx.x * blockDim.x + threadIdx.x;
    if (idx >= HH * HH) return;
    float g = 0.02f * fabsf(Wh[idx]);
    float q = fabsf(kap[idx]);
    unsigned short gs = __bfloat16_as_ushort(__float2bfloat16_rn(g));
    unsigned short qs = __bfloat16_as_ushort(__float2bfloat16_rn(q));
    g_gq[idx] = (unsigned int)gs | ((unsigned int)qs << 16);
}

// ---------------- prep: signed output + feedforward drive ----------------
__global__ void prep_soff(const float* __restrict__ x, const float* __restrict__ outp,
                          const float* __restrict__ aux,
                          const float* __restrict__ Wx, const float* __restrict__ Waux,
                          const float* __restrict__ bh, const float* __restrict__ mask) {
    int idx = blockIdx.x * blockDim.x + threadIdx.x;
    if (idx >= BH) return;
    int b = idx >> 10;
    int i = idx & (HH - 1);
    // mask_h[r, j] = sign_j for any r != j (zero diagonal) -> read row (i+1)%H
    float sgn = mask[((i + 1) & (HH - 1)) * HH + i];
    g_so[idx] = sgn * outp[idx];

    float acc = bh[i];
    const float* wr = Wx + i * II;
    const float* xr = x + b * II;
#pragma unroll 8
    for (int k = 0; k < II; k++) acc += fmaxf(xr[k], 0.f) * fabsf(wr[k]);
    const float* wa = Waux + i * AA;
    const float* ar = aux + b * AA;
#pragma unroll
    for (int k = 0; k < AA; k++) acc += fmaxf(ar[k], 0.f) * fabsf(wa[k]);
    g_ff[idx] = acc;
}

// ---------------- pass 1 (per group): new_state / new_output ----------------
// Default (caching) loads so the group's wh tile fills L2 for k_plast's re-read.
__global__ __launch_bounds__(256) void k_state(const float* __restrict__ wh,
                                               const float* __restrict__ state,
                                               float* __restrict__ out_state,
                                               float* __restrict__ out_output,
                                               int row_base) {
    __shared__ float so_sh[HH];
    const int warp = threadIdx.x >> 5;
    const int lane = threadIdx.x & 31;
    const int row0 = row_base + blockIdx.x * 8;   // 8 warps = 8 rows, same batch
    const int b = row0 >> 10;
    const int row = row0 + warp;
    const int i = row & (HH - 1);

    for (int k = threadIdx.x; k < HH; k += 256) so_sh[k] = g_so[(b << 10) + k];
    __syncthreads();

    const float4* w4 = (const float4*)(wh + (size_t)row * HH);
    const float4* s4 = (const float4*)so_sh;
    float acc = 0.f;
#pragma unroll
    for (int k = 0; k < 8; k++) {
        float4 w = w4[lane + 32 * k];
        float4 s = s4[lane + 32 * k];
        acc += w.x * s.x + w.y * s.y + w.z * s.z + w.w * s.w;
    }
#pragma unroll
    for (int off = 16; off; off >>= 1) acc += __shfl_down_sync(0xffffffffu, acc, off);

    if (lane == 0) {
        float diag = wh[(size_t)row * HH + i] * so_sh[i];   // remove diagonal (mask=0 there)
        float total = acc - diag + g_ff[row];
        float ns = 0.8f * state[row] + 0.2f * total;
        out_state[row] = ns;
        out_output[row] = ns > 0.f ? tanhf(ns) : 0.f;       // retanh
    }
}

// ---------------- pass 2 (per group): plasticity update ----------------
// wh reads should hit L2 (filled by k_state of same group); writes stream out.
__global__ __launch_bounds__(256) void k_plast(const float* __restrict__ wh,
                                               const float* __restrict__ da,
                                               const float* __restrict__ newout,
                                               float* __restrict__ out_w,
                                               int row_base) {
    const int row = row_base + blockIdx.x;        // (b,i)
    const int b = row >> 10;
    const int i = row & (HH - 1);
    const float no_i = newout[row];
    const float coef = 0.02f * da[b] * no_i;      // DT * da * new_output_i

    const int t = threadIdx.x;                    // 256 threads x 4 cols
    const size_t base = (size_t)row * HH + 4 * t;

    float4 w = __ldcs((const float4*)(wh + base));
    uint4 gq = *(const uint4*)(g_gq + i * HH + 4 * t);
    float4 no = *(const float4*)(newout + (b << 10) + 4 * t);

    float4 r;
    {
        float g = __bfloat162float(__ushort_as_bfloat16((unsigned short)(gq.x & 0xffff)));
        float q = __bfloat162float(__ushort_as_bfloat16((unsigned short)(gq.x >> 16)));
        r.x = fminf(fmaxf(g + 0.98f * w.x + coef * q * no.x, 0.f), 1.f);
    }
    {
        float g = __bfloat162float(__ushort_as_bfloat16((unsigned short)(gq.y & 0xffff)));
        float q = __bfloat162float(__ushort_as_bfloat16((unsigned short)(gq.y >> 16)));
        r.y = fminf(fmaxf(g + 0.98f * w.y + coef * q * no.y, 0.f), 1.f);
    }
    {
        float g = __bfloat162float(__ushort_as_bfloat16((unsigned short)(gq.z & 0xffff)));
        float q = __bfloat162float(__ushort_as_bfloat16((unsigned short)(gq.z >> 16)));
        r.z = fminf(fmaxf(g + 0.98f * w.z + coef * q * no.z, 0.f), 1.f);
    }
    {
        float g = __bfloat162float(__ushort_as_bfloat16((unsigned short)(gq.w & 0xffff)));
        float q = __bfloat162float(__ushort_as_bfloat16((unsigned short)(gq.w >> 16)));
        r.w = fminf(fmaxf(g + 0.98f * w.w + coef * q * no.w, 0.f), 1.f);
    }
    __stcs((float4*)(out_w + base), r);
}

extern "C" void kernel_launch(void* const* d_in, const int* in_sizes, int n_in,
                              void* d_out, int out_size) {
    const float* x      = (const float*)d_in[0];   // [B,I]
    const float* state  = (const float*)d_in[1];   // [B,H]
    const float* outp   = (const float*)d_in[2];   // [B,H]
    const float* wh     = (const float*)d_in[3];   // [B,H,H]
    const float* da     = (const float*)d_in[4];   // [B]
    const float* aux    = (const float*)d_in[5];   // [B,A]
    const float* Wx     = (const float*)d_in[6];   // [H,I]
    const float* Waux   = (const float*)d_in[7];   // [H,A]
    const float* Wh     = (const float*)d_in[8];   // [H,H]
    const float* bh     = (const float*)d_in[9];   // [H]
    const float* kappa  = (const float*)d_in[10];  // [H,H]
    const float* mask   = (const float*)d_in[11];  // [H,H]

    float* out_state  = (float*)d_out;                 // [B,H]
    float* out_output = (float*)d_out + BH;            // [B,H]
    float* out_w      = (float*)d_out + 2 * BH;        // [B,H,H]

    prep_gq<<<(HH * HH + 255) / 256, 256>>>(Wh, kappa);
    prep_soff<<<(BH + 255) / 256, 256>>>(x, outp, aux, Wx, Waux, bh, mask);

    // L2-resident ping-pong: state(g) pulls wh[g] (32MB) through L2,
    // plast(g) re-reads it as L2 hits and streams new_w out.
    for (int g = 0; g < NGROUPS; g++) {
        int row_base = g * GB * HH;
        k_state<<<GB * HH / 8, 256>>>(wh, state, out_state, out_output, row_base);
        k_plast<<<GB * HH, 256>>>(wh, da, out_output, out_w, row_base);
    }
}

// round 5
// speedup vs baseline: 1.0714x; 1.0714x over previous
#include <cuda_runtime.h>
#include <cuda_bf16.h>
#include <cstdint>

#define BB 64
#define II 128
#define AA 16
#define HH 1024
#define BH (BB*HH)

// scratch (static __device__ — no allocations)
__device__ float g_so[BH];              // sign_j * output[b,j]
__device__ float g_ff[BH];              // b_h + relu(x)@|W_x|^T + relu(aux)@|W_aux|^T
__device__ unsigned int g_gq[HH*HH];    // packed bf16: lo = 0.02*|W_h|, hi = |kappa|
__device__ unsigned int g_cnt[BB];      // per-batch arrival counters (software barrier)

// ---------------- prep: pack (0.02*|W_h|, |kappa|) as bf16x2; zero counters ----------------
__global__ void prep_gq(const float* __restrict__ Wh, const float* __restrict__ kap) {
    int idx = blockIdx.x * blockDim.x + threadIdx.x;
    if (idx < BB) g_cnt[idx] = 0u;                       // reset barrier state every call
    if (idx >= HH * HH) return;
    float g = 0.02f * fabsf(Wh[idx]);
    float q = fabsf(kap[idx]);
    unsigned short gs = __bfloat16_as_ushort(__float2bfloat16_rn(g));
    unsigned short qs = __bfloat16_as_ushort(__float2bfloat16_rn(q));
    g_gq[idx] = (unsigned int)gs | ((unsigned int)qs << 16);
}

// ---------------- prep: signed output + feedforward drive ----------------
__global__ void prep_soff(const float* __restrict__ x, const float* __restrict__ outp,
                          const float* __restrict__ aux,
                          const float* __restrict__ Wx, const float* __restrict__ Waux,
                          const float* __restrict__ bh, const float* __restrict__ mask) {
    int idx = blockIdx.x * blockDim.x + threadIdx.x;
    if (idx >= BH) return;
    int b = idx >> 10;
    int i = idx & (HH - 1);
    // mask_h[r, j] = sign_j for any r != j (zero diagonal) -> read row (i+1)%H
    float sgn = mask[((i + 1) & (HH - 1)) * HH + i];
    g_so[idx] = sgn * outp[idx];

    float acc = bh[i];
    const float* wr = Wx + i * II;
    const float* xr = x + b * II;
#pragma unroll 8
    for (int k = 0; k < II; k++) acc += fmaxf(xr[k], 0.f) * fabsf(wr[k]);
    const float* wa = Waux + i * AA;
    const float* ar = aux + b * AA;
#pragma unroll
    for (int k = 0; k < AA; k++) acc += fmaxf(ar[k], 0.f) * fabsf(wa[k]);
    g_ff[idx] = acc;
}

// ---------------- fused: matvec -> per-batch barrier -> plasticity (wh stays in regs) ----------------
__global__ __launch_bounds__(256, 4) void k_fused(const float* __restrict__ wh,
                                                  const float* __restrict__ state,
                                                  const float* __restrict__ da,
                                                  float* __restrict__ out_state,
                                                  float* __restrict__ out_output,
                                                  float* __restrict__ out_w) {
    __shared__ float so_sh[HH];
    const int warp = threadIdx.x >> 5;
    const int lane = threadIdx.x & 31;
    const int row0 = blockIdx.x * 8;              // 8 warps = 8 rows, same batch
    const int b = row0 >> 10;
    const int row = row0 + warp;
    const int i = row & (HH - 1);

    for (int k = threadIdx.x; k < HH; k += 256) so_sh[k] = g_so[(b << 10) + k];
    __syncthreads();

    // ---- pass 1: matvec; keep this row's wh slice in registers ----
    const float4* w4 = (const float4*)(wh + (size_t)row * HH);
    float4 w[8];
    float acc = 0.f;
#pragma unroll
    for (int k = 0; k < 8; k++) {
        w[k] = w4[lane + 32 * k];
        float4 s = ((const float4*)so_sh)[lane + 32 * k];
        acc += w[k].x * s.x + w[k].y * s.y + w[k].z * s.z + w[k].w * s.w;
    }
    // remove diagonal contribution (mask_h has zero diagonal) — from registers
#pragma unroll
    for (int k = 0; k < 8; k++) {
        int c = 4 * (lane + 32 * k);
        if (i >= c && i < c + 4) {
            float wv = (i - c == 0) ? w[k].x : (i - c == 1) ? w[k].y : (i - c == 2) ? w[k].z : w[k].w;
            acc -= wv * so_sh[i];
        }
    }
#pragma unroll
    for (int off = 16; off; off >>= 1) acc += __shfl_down_sync(0xffffffffu, acc, off);

    float no_i = 0.f;
    if (lane == 0) {
        float total = acc + g_ff[row];
        float ns = 0.8f * state[row] + 0.2f * total;
        out_state[row] = ns;
        no_i = ns > 0.f ? tanhf(ns) : 0.f;        // retanh
        out_output[row] = no_i;
    }
    no_i = __shfl_sync(0xffffffffu, no_i, 0);
    __syncthreads();                               // all 8 rows of this block written

    // ---- per-batch software barrier: arrive (release), then wait (acquire) ----
    if (threadIdx.x == 0) {
        __threadfence();                           // publish out_output writes
        atomicAdd(&g_cnt[b], 1u);                  // arrive BEFORE wait -> no circular wait
        unsigned v;
        do {
            asm volatile("ld.global.acquire.gpu.u32 %0, [%1];" : "=r"(v) : "l"(g_cnt + b));
        } while (v < 128u);
    }
    __syncthreads();

    // ---- pass 2: plasticity from register-held wh ----
    const float coef = 0.02f * da[b] * no_i;       // DT * da * new_output_i
    const float* nob = out_output + (b << 10);
    const unsigned* gqr = g_gq + i * HH;
    const size_t base = (size_t)row * HH;

#pragma unroll
    for (int k = 0; k < 8; k++) {
        int c = 4 * (lane + 32 * k);
        float4 no4 = __ldcg((const float4*)(nob + c));     // bypass L1 (cross-block data)
        uint4 gq = *(const uint4*)(gqr + c);
        float4 r;
        {
            float g = __bfloat162float(__ushort_as_bfloat16((unsigned short)(gq.x & 0xffff)));
            float q = __bfloat162float(__ushort_as_bfloat16((unsigned short)(gq.x >> 16)));
            r.x = fminf(fmaxf(g + 0.98f * w[k].x + coef * q * no4.x, 0.f), 1.f);
        }
        {
            float g = __bfloat162float(__ushort_as_bfloat16((unsigned short)(gq.y & 0xffff)));
            float q = __bfloat162float(__ushort_as_bfloat16((unsigned short)(gq.y >> 16)));
            r.y = fminf(fmaxf(g + 0.98f * w[k].y + coef * q * no4.y, 0.f), 1.f);
        }
        {
            float g = __bfloat162float(__ushort_as_bfloat16((unsigned short)(gq.z & 0xffff)));
            float q = __bfloat162float(__ushort_as_bfloat16((unsigned short)(gq.z >> 16)));
            r.z = fminf(fmaxf(g + 0.98f * w[k].z + coef * q * no4.z, 0.f), 1.f);
        }
        {
            float g = __bfloat162float(__ushort_as_bfloat16((unsigned short)(gq.w & 0xffff)));
            float q = __bfloat162float(__ushort_as_bfloat16((unsigned short)(gq.w >> 16)));
            r.w = fminf(fmaxf(g + 0.98f * w[k].w + coef * q * no4.w, 0.f), 1.f);
        }
        __stcs((float4*)(out_w + base + c), r);
    }
}

extern "C" void kernel_launch(void* const* d_in, const int* in_sizes, int n_in,
                              void* d_out, int out_size) {
    const float* x      = (const float*)d_in[0];   // [B,I]
    const float* state  = (const float*)d_in[1];   // [B,H]
    const float* outp   = (const float*)d_in[2];   // [B,H]
    const float* wh     = (const float*)d_in[3];   // [B,H,H]
    const float* da     = (const float*)d_in[4];   // [B]
    const float* aux    = (const float*)d_in[5];   // [B,A]
    const float* Wx     = (const float*)d_in[6];   // [H,I]
    const float* Waux   = (const float*)d_in[7];   // [H,A]
    const float* Wh     = (const float*)d_in[8];   // [H,H]
    const float* bh     = (const float*)d_in[9];   // [H]
    const float* kappa  = (const float*)d_in[10];  // [H,H]
    const float* mask   = (const float*)d_in[11];  // [H,H]

    float* out_state  = (float*)d_out;                 // [B,H]
    float* out_output = (float*)d_out + BH;            // [B,H]
    float* out_w      = (float*)d_out + 2 * BH;        // [B,H,H]

    prep_gq<<<(HH * HH + 255) / 256, 256>>>(Wh, kappa);
    prep_soff<<<(BH + 255) / 256, 256>>>(x, outp, aux, Wx, Waux, bh, mask);
    k_fused<<<BH / 8, 256>>>(wh, state, da, out_state, out_output, out_w);
}

// round 6
// speedup vs baseline: 1.1688x; 1.0909x over previous
#include <cuda_runtime.h>
#include <cuda_bf16.h>
#include <cstdint>

#define BB 64
#define II 128
#define AA 16
#define HH 1024
#define BH (BB*HH)

// scratch (static __device__ — no allocations)
__device__ float g_so[BH];              // sign_j * output[b,j]
__device__ float g_ff[BH];              // b_h + relu(x)@|W_x|^T + relu(aux)@|W_aux|^T
__device__ unsigned int g_gq[HH*HH];    // packed bf16: lo = 0.02*|W_h|, hi = |kappa|

// ---------------- prep: pack (0.02*|W_h|, |kappa|) as bf16x2 (vectorized) ----------------
__global__ void prep_gq(const float4* __restrict__ Wh, const float4* __restrict__ kap) {
    int idx = blockIdx.x * blockDim.x + threadIdx.x;    // over HH*HH/4
    if (idx >= HH * HH / 4) return;
    float4 wv = Wh[idx];
    float4 kv = kap[idx];
    uint4 o;
    o.x = (unsigned)__bfloat16_as_ushort(__float2bfloat16_rn(0.02f * fabsf(wv.x)))
        | ((unsigned)__bfloat16_as_ushort(__float2bfloat16_rn(fabsf(kv.x))) << 16);
    o.y = (unsigned)__bfloat16_as_ushort(__float2bfloat16_rn(0.02f * fabsf(wv.y)))
        | ((unsigned)__bfloat16_as_ushort(__float2bfloat16_rn(fabsf(kv.y))) << 16);
    o.z = (unsigned)__bfloat16_as_ushort(__float2bfloat16_rn(0.02f * fabsf(wv.z)))
        | ((unsigned)__bfloat16_as_ushort(__float2bfloat16_rn(fabsf(kv.z))) << 16);
    o.w = (unsigned)__bfloat16_as_ushort(__float2bfloat16_rn(0.02f * fabsf(wv.w)))
        | ((unsigned)__bfloat16_as_ushort(__float2bfloat16_rn(fabsf(kv.w))) << 16);
    ((uint4*)g_gq)[idx] = o;
}

// ---------------- prep: signed output + feedforward drive (warp per output) ----------------
__global__ __launch_bounds__(256) void prep_soff(const float* __restrict__ x,
                                                 const float* __restrict__ outp,
                                                 const float* __restrict__ aux,
                                                 const float* __restrict__ Wx,
                                                 const float* __restrict__ Waux,
                                                 const float* __restrict__ bh,
                                                 const float* __restrict__ mask) {
    const int warp = threadIdx.x >> 5;
    const int lane = threadIdx.x & 31;
    const int row = blockIdx.x * 8 + warp;        // (b,i)
    const int b = row >> 10;
    const int i = row & (HH - 1);

    // W_x row: 128 floats = 32 lanes x float4 (coalesced)
    float4 w = ((const float4*)(Wx + i * II))[lane];
    float4 xv = ((const float4*)(x + b * II))[lane];
    float acc = fmaxf(xv.x, 0.f) * fabsf(w.x) + fmaxf(xv.y, 0.f) * fabsf(w.y)
              + fmaxf(xv.z, 0.f) * fabsf(w.z) + fmaxf(xv.w, 0.f) * fabsf(w.w);
    // W_aux row: 16 floats = 4 lanes x float4
    if (lane < 4) {
        float4 wa = ((const float4*)(Waux + i * AA))[lane];
        float4 av = ((const float4*)(aux + b * AA))[lane];
        acc += fmaxf(av.x, 0.f) * fabsf(wa.x) + fmaxf(av.y, 0.f) * fabsf(wa.y)
             + fmaxf(av.z, 0.f) * fabsf(wa.z) + fmaxf(av.w, 0.f) * fabsf(wa.w);
    }
#pragma unroll
    for (int off = 16; off; off >>= 1) acc += __shfl_down_sync(0xffffffffu, acc, off);
    if (lane == 0) {
        g_ff[row] = acc + bh[i];
        // mask_h[r, j] = sign_j for any r != j (zero diagonal) -> read row (i+1)%H
        float sgn = mask[((i + 1) & (HH - 1)) * HH + i];
        g_so[row] = sgn * outp[row];
    }
}

// ---------------- pass 1: new_state / new_output (block per row, k_plast shape) ----------------
__global__ __launch_bounds__(256) void k_state2(const float* __restrict__ wh,
                                                const float* __restrict__ state,
                                                float* __restrict__ out_state,
                                                float* __restrict__ out_output) {
    __shared__ float red[8];
    const int row = blockIdx.x;                   // (b,i)
    const int b = row >> 10;
    const int i = row & (HH - 1);
    const int t = threadIdx.x;                    // 256 threads x 4 cols

    float4 w = *(const float4*)(wh + (size_t)row * HH + 4 * t);
    float4 s = *(const float4*)(g_so + (b << 10) + 4 * t);
    float acc = w.x * s.x + w.y * s.y + w.z * s.z + w.w * s.w;
    // zero-diagonal: this thread owns column i iff t == i>>2
    if (t == (i >> 2)) {
        int r = i & 3;
        float wv = (r == 0) ? w.x : (r == 1) ? w.y : (r == 2) ? w.z : w.w;
        float sv = (r == 0) ? s.x : (r == 1) ? s.y : (r == 2) ? s.z : s.w;
        acc -= wv * sv;
    }
#pragma unroll
    for (int off = 16; off; off >>= 1) acc += __shfl_down_sync(0xffffffffu, acc, off);
    if ((t & 31) == 0) red[t >> 5] = acc;
    __syncthreads();
    if (t == 0) {
        float total = red[0] + red[1] + red[2] + red[3]
                    + red[4] + red[5] + red[6] + red[7] + g_ff[row];
        float ns = 0.8f * state[row] + 0.2f * total;
        out_state[row] = ns;
        out_output[row] = ns > 0.f ? tanhf(ns) : 0.f;   // retanh
    }
}

// ---------------- pass 2: plasticity update (element-wise stream) ----------------
__global__ __launch_bounds__(256) void k_plast(const float* __restrict__ wh,
                                               const float* __restrict__ da,
                                               const float* __restrict__ newout,
                                               float* __restrict__ out_w) {
    const int row = blockIdx.x;                   // (b,i)
    const int b = row >> 10;
    const int i = row & (HH - 1);
    const float no_i = newout[row];
    const float coef = 0.02f * da[b] * no_i;      // DT * da * new_output_i

    const int t = threadIdx.x;                    // 256 threads x 4 cols
    const size_t base = (size_t)row * HH + 4 * t;

    float4 w = __ldcs((const float4*)(wh + base));
    uint4 gq = *(const uint4*)(g_gq + i * HH + 4 * t);
    float4 no = *(const float4*)(newout + (b << 10) + 4 * t);

    float4 r;
    {
        float g = __bfloat162float(__ushort_as_bfloat16((unsigned short)(gq.x & 0xffff)));
        float q = __bfloat162float(__ushort_as_bfloat16((unsigned short)(gq.x >> 16)));
        r.x = fminf(fmaxf(g + 0.98f * w.x + coef * q * no.x, 0.f), 1.f);
    }
    {
        float g = __bfloat162float(__ushort_as_bfloat16((unsigned short)(gq.y & 0xffff)));
        float q = __bfloat162float(__ushort_as_bfloat16((unsigned short)(gq.y >> 16)));
        r.y = fminf(fmaxf(g + 0.98f * w.y + coef * q * no.y, 0.f), 1.f);
    }
    {
        float g = __bfloat162float(__ushort_as_bfloat16((unsigned short)(gq.z & 0xffff)));
        float q = __bfloat162float(__ushort_as_bfloat16((unsigned short)(gq.z >> 16)));
        r.z = fminf(fmaxf(g + 0.98f * w.z + coef * q * no.z, 0.f), 1.f);
    }
    {
        float g = __bfloat162float(__ushort_as_bfloat16((unsigned short)(gq.w & 0xffff)));
        float q = __bfloat162float(__ushort_as_bfloat16((unsigned short)(gq.w >> 16)));
        r.w = fminf(fmaxf(g + 0.98f * w.w + coef * q * no.w, 0.f), 1.f);
    }
    __stcs((float4*)(out_w + base), r);
}

extern "C" void kernel_launch(void* const* d_in, const int* in_sizes, int n_in,
                              void* d_out, int out_size) {
    const float* x      = (const float*)d_in[0];   // [B,I]
    const float* state  = (const float*)d_in[1];   // [B,H]
    const float* outp   = (const float*)d_in[2];   // [B,H]
    const float* wh     = (const float*)d_in[3];   // [B,H,H]
    const float* da     = (const float*)d_in[4];   // [B]
    const float* aux    = (const float*)d_in[5];   // [B,A]
    const float* Wx     = (const float*)d_in[6];   // [H,I]
    const float* Waux   = (const float*)d_in[7];   // [H,A]
    const float* Wh     = (const float*)d_in[8];   // [H,H]
    const float* bh     = (const float*)d_in[9];   // [H]
    const float* kappa  = (const float*)d_in[10];  // [H,H]
    const float* mask   = (const float*)d_in[11];  // [H,H]

    float* out_state  = (float*)d_out;                 // [B,H]
    float* out_output = (float*)d_out + BH;            // [B,H]
    float* out_w      = (float*)d_out + 2 * BH;        // [B,H,H]

    prep_soff<<<BH / 8, 256>>>(x, outp, aux, Wx, Waux, bh, mask);
    prep_gq<<<(HH * HH / 4 + 255) / 256, 256>>>((const float4*)Wh, (const float4*)kappa);
    k_state2<<<BH, 256>>>(wh, state, out_state, out_output);
    k_plast<<<BH, 256>>>(wh, da, out_output, out_w);
}

// round 7
// speedup vs baseline: 1.4255x; 1.2196x over previous
#include <cuda_runtime.h>
#include <cuda_bf16.h>
#include <cstdint>

#define BB 64
#define II 128
#define AA 16
#define HH 1024
#define BH (BB*HH)

// scratch (static __device__ — no allocations)
__device__ float g_so[BH];              // sign_j * output[b,j]
__device__ float g_ff[BH];              // b_h + relu(x)@|W_x|^T + relu(aux)@|W_aux|^T
__device__ unsigned int g_gq[HH*HH];    // packed bf16: lo = 0.02*|W_h|, hi = |kappa|

// ---------------- prep: pack (0.02*|W_h|, |kappa|) as bf16x2 (vectorized) ----------------
__global__ void prep_gq(const float4* __restrict__ Wh, const float4* __restrict__ kap) {
    int idx = blockIdx.x * blockDim.x + threadIdx.x;    // over HH*HH/4
    if (idx >= HH * HH / 4) return;
    float4 wv = Wh[idx];
    float4 kv = kap[idx];
    uint4 o;
    o.x = (unsigned)__bfloat16_as_ushort(__float2bfloat16_rn(0.02f * fabsf(wv.x)))
        | ((unsigned)__bfloat16_as_ushort(__float2bfloat16_rn(fabsf(kv.x))) << 16);
    o.y = (unsigned)__bfloat16_as_ushort(__float2bfloat16_rn(0.02f * fabsf(wv.y)))
        | ((unsigned)__bfloat16_as_ushort(__float2bfloat16_rn(fabsf(kv.y))) << 16);
    o.z = (unsigned)__bfloat16_as_ushort(__float2bfloat16_rn(0.02f * fabsf(wv.z)))
        | ((unsigned)__bfloat16_as_ushort(__float2bfloat16_rn(fabsf(kv.z))) << 16);
    o.w = (unsigned)__bfloat16_as_ushort(__float2bfloat16_rn(0.02f * fabsf(wv.w)))
        | ((unsigned)__bfloat16_as_ushort(__float2bfloat16_rn(fabsf(kv.w))) << 16);
    ((uint4*)g_gq)[idx] = o;
}

// ---------------- prep: signed output + feedforward drive (warp per output) ----------------
__global__ __launch_bounds__(256) void prep_soff(const float* __restrict__ x,
                                                 const float* __restrict__ outp,
                                                 const float* __restrict__ aux,
                                                 const float* __restrict__ Wx,
                                                 const float* __restrict__ Waux,
                                                 const float* __restrict__ bh,
                                                 const float* __restrict__ mask) {
    const int warp = threadIdx.x >> 5;
    const int lane = threadIdx.x & 31;
    const int row = blockIdx.x * 8 + warp;        // (b,i)
    const int b = row >> 10;
    const int i = row & (HH - 1);

    float4 w = ((const float4*)(Wx + i * II))[lane];
    float4 xv = ((const float4*)(x + b * II))[lane];
    float acc = fmaxf(xv.x, 0.f) * fabsf(w.x) + fmaxf(xv.y, 0.f) * fabsf(w.y)
              + fmaxf(xv.z, 0.f) * fabsf(w.z) + fmaxf(xv.w, 0.f) * fabsf(w.w);
    if (lane < 4) {
        float4 wa = ((const float4*)(Waux + i * AA))[lane];
        float4 av = ((const float4*)(aux + b * AA))[lane];
        acc += fmaxf(av.x, 0.f) * fabsf(wa.x) + fmaxf(av.y, 0.f) * fabsf(wa.y)
             + fmaxf(av.z, 0.f) * fabsf(wa.z) + fmaxf(av.w, 0.f) * fabsf(wa.w);
    }
#pragma unroll
    for (int off = 16; off; off >>= 1) acc += __shfl_down_sync(0xffffffffu, acc, off);
    if (lane == 0) {
        g_ff[row] = acc + bh[i];
        // mask_h[r, j] = sign_j for any r != j (zero diagonal) -> read row (i+1)%H
        float sgn = mask[((i + 1) & (HH - 1)) * HH + i];
        g_so[row] = sgn * outp[row];
    }
}

// ---------------- pass 1: 4 rows per block -> 4 LDG.128 in flight per thread ----------------
__global__ __launch_bounds__(256) void k_state4(const float* __restrict__ wh,
                                                const float* __restrict__ state,
                                                float* __restrict__ out_state,
                                                float* __restrict__ out_output) {
    __shared__ float red[8 * 4];
    const int row0 = blockIdx.x * 4;              // 4 consecutive rows, same batch (4 | 1024)
    const int b = row0 >> 10;
    const int t = threadIdx.x;                    // 256 threads x 4 cols

    // front-batched independent loads: 4 wh rows + shared so vector
    const float4* wp = (const float4*)(wh + (size_t)row0 * HH) + t;
    float4 w0 = wp[0];
    float4 w1 = wp[256];
    float4 w2 = wp[512];
    float4 w3 = wp[768];
    float4 s  = *(const float4*)(g_so + (b << 10) + 4 * t);

    float a0 = w0.x * s.x + w0.y * s.y + w0.z * s.z + w0.w * s.w;
    float a1 = w1.x * s.x + w1.y * s.y + w1.z * s.z + w1.w * s.w;
    float a2 = w2.x * s.x + w2.y * s.y + w2.z * s.z + w2.w * s.w;
    float a3 = w3.x * s.x + w3.y * s.y + w3.z * s.z + w3.w * s.w;

    // zero-diagonal fixups (owner thread of column i subtracts locally)
#pragma unroll
    for (int r = 0; r < 4; r++) {
        int i = (row0 + r) & (HH - 1);
        if (t == (i >> 2)) {
            int c = i & 3;
            float4 w = (r == 0) ? w0 : (r == 1) ? w1 : (r == 2) ? w2 : w3;
            float wv = (c == 0) ? w.x : (c == 1) ? w.y : (c == 2) ? w.z : w.w;
            float sv = (c == 0) ? s.x : (c == 1) ? s.y : (c == 2) ? s.z : s.w;
            float d = wv * sv;
            if (r == 0) a0 -= d; else if (r == 1) a1 -= d; else if (r == 2) a2 -= d; else a3 -= d;
        }
    }
#pragma unroll
    for (int off = 16; off; off >>= 1) {
        a0 += __shfl_down_sync(0xffffffffu, a0, off);
        a1 += __shfl_down_sync(0xffffffffu, a1, off);
        a2 += __shfl_down_sync(0xffffffffu, a2, off);
        a3 += __shfl_down_sync(0xffffffffu, a3, off);
    }
    if ((t & 31) == 0) {
        int w = t >> 5;
        red[w * 4 + 0] = a0; red[w * 4 + 1] = a1;
        red[w * 4 + 2] = a2; red[w * 4 + 3] = a3;
    }
    __syncthreads();
    if (t < 4) {
        float total = g_ff[row0 + t];
#pragma unroll
        for (int w = 0; w < 8; w++) total += red[w * 4 + t];
        float ns = 0.8f * state[row0 + t] + 0.2f * total;
        out_state[row0 + t] = ns;
        out_output[row0 + t] = ns > 0.f ? tanhf(ns) : 0.f;   // retanh
    }
}

// ---------------- pass 2: plasticity, 128 threads x 2 chunks -> 2x read MLP ----------------
__device__ __forceinline__ float4 plast4(float4 w, uint4 gq, float4 no, float coef) {
    float4 r;
    {
        float g = __bfloat162float(__ushort_as_bfloat16((unsigned short)(gq.x & 0xffff)));
        float q = __bfloat162float(__ushort_as_bfloat16((unsigned short)(gq.x >> 16)));
        r.x = fminf(fmaxf(g + 0.98f * w.x + coef * q * no.x, 0.f), 1.f);
    }
    {
        float g = __bfloat162float(__ushort_as_bfloat16((unsigned short)(gq.y & 0xffff)));
        float q = __bfloat162float(__ushort_as_bfloat16((unsigned short)(gq.y >> 16)));
        r.y = fminf(fmaxf(g + 0.98f * w.y + coef * q * no.y, 0.f), 1.f);
    }
    {
        float g = __bfloat162float(__ushort_as_bfloat16((unsigned short)(gq.z & 0xffff)));
        float q = __bfloat162float(__ushort_as_bfloat16((unsigned short)(gq.z >> 16)));
        r.z = fminf(fmaxf(g + 0.98f * w.z + coef * q * no.z, 0.f), 1.f);
    }
    {
        float g = __bfloat162float(__ushort_as_bfloat16((unsigned short)(gq.w & 0xffff)));
        float q = __bfloat162float(__ushort_as_bfloat16((unsigned short)(gq.w >> 16)));
        r.w = fminf(fmaxf(g + 0.98f * w.w + coef * q * no.w, 0.f), 1.f);
    }
    return r;
}

__global__ __launch_bounds__(128) void k_plast(const float* __restrict__ wh,
                                               const float* __restrict__ da,
                                               const float* __restrict__ newout,
                                               float* __restrict__ out_w) {
    const int row = blockIdx.x;                   // (b,i)
    const int b = row >> 10;
    const int i = row & (HH - 1);
    const float no_i = newout[row];
    const float coef = 0.02f * da[b] * no_i;      // DT * da * new_output_i

    const int t = threadIdx.x;                    // 128 threads x 2 float4 chunks
    const size_t base = (size_t)row * HH;

    // front-batch both DRAM reads (independent -> MLP=2)
    float4 wA = __ldcs((const float4*)(wh + base + 4 * t));
    float4 wB = __ldcs((const float4*)(wh + base + 512 + 4 * t));
    uint4 gqA = *(const uint4*)(g_gq + i * HH + 4 * t);
    uint4 gqB = *(const uint4*)(g_gq + i * HH + 512 + 4 * t);
    float4 noA = *(const float4*)(newout + (b << 10) + 4 * t);
    float4 noB = *(const float4*)(newout + (b << 10) + 512 + 4 * t);

    __stcs((float4*)(out_w + base + 4 * t),       plast4(wA, gqA, noA, coef));
    __stcs((float4*)(out_w + base + 512 + 4 * t), plast4(wB, gqB, noB, coef));
}

extern "C" void kernel_launch(void* const* d_in, const int* in_sizes, int n_in,
                              void* d_out, int out_size) {
    const float* x      = (const float*)d_in[0];   // [B,I]
    const float* state  = (const float*)d_in[1];   // [B,H]
    const float* outp   = (const float*)d_in[2];   // [B,H]
    const float* wh     = (const float*)d_in[3];   // [B,H,H]
    const float* da     = (const float*)d_in[4];   // [B]
    const float* aux    = (const float*)d_in[5];   // [B,A]
    const float* Wx     = (const float*)d_in[6];   // [H,I]
    const float* Waux   = (const float*)d_in[7];   // [H,A]
    const float* Wh     = (const float*)d_in[8];   // [H,H]
    const float* bh     = (const float*)d_in[9];   // [H]
    const float* kappa  = (const float*)d_in[10];  // [H,H]
    const float* mask   = (const float*)d_in[11];  // [H,H]

    float* out_state  = (float*)d_out;                 // [B,H]
    float* out_output = (float*)d_out + BH;            // [B,H]
    float* out_w      = (float*)d_out + 2 * BH;        // [B,H,H]

    prep_soff<<<BH / 8, 256>>>(x, outp, aux, Wx, Waux, bh, mask);
    prep_gq<<<(HH * HH / 4 + 255) / 256, 256>>>((const float4*)Wh, (const float4*)kappa);
    k_state4<<<BH / 4, 256>>>(wh, state, out_state, out_output);
    k_plast<<<BH, 128>>>(wh, da, out_output, out_w);
}